// round 7
// baseline (speedup 1.0000x reference)
#include <cuda_runtime.h>
#include <cuda_fp16.h>
#include <cstdint>

// x:      (2, 64, 32, 32, 32) fp32
// weight: (64, 32, 3, 3, 3)   fp32
// bias:   (32,)               fp32
// out:    (2, 32, 66, 66, 66) fp32
//
// Core: out[n,co,2z+1] = bias[co] + sum_{ci,tap} W[ci,co,26-tap] * x[n,ci,z-1+k]
// All other outputs bias-only.
//
// GEMM per CTA: D[m=(h,w), co] = sum over 27 taps of A_tap[m, ci] * B_tap[co, ci]
// via mma.sync.m16n8k16 (fp16 in, fp32 accum), fp16 hi/lo split, 3 passes.

#define OUT_S 66
#define CH_STRIDE 287496
#define OUT_TOTAL 18399744
#define OUT_F4 (OUT_TOTAL / 4)
#define CH_F4 (CH_STRIDE / 4)

// dynamic smem layout (bytes)
#define SM_BHI 0            // 288 rows x 128B = 36864  (9 taps x 32 co)
#define SM_BLO 36864
#define SM_AHI 73728        // 204 rows x 128B = 26112  (6 hp x 34 wp)
#define SM_ALO 99840
#define SM_TOTAL 125952

// Pre-converted, flipped, swizzled weights: [half][kd][row=tl*32+co][128B]
// row's 64 fp16 = ci values of W[ci,co,26-(kd*9+tl)], byte off = ci*2 ^ ((row&7)<<4)
__device__ __align__(16) unsigned char g_wprep[2][3][36864];

// ---------------------------------------------------------------------------
__global__ void wprep_kernel(const float* __restrict__ w) {
    int i = blockIdx.x * blockDim.x + threadIdx.x;   // 3*288*64 = 55296
    if (i >= 55296) return;
    int kd  = i / 18432;
    int rem = i - kd * 18432;
    int r   = rem >> 6;          // 0..287
    int ci  = rem & 63;
    int tl  = r >> 5;            // kh*3+kw
    int co  = r & 31;
    int tap = kd * 9 + tl;
    float v = w[(ci * 32 + co) * 27 + (26 - tap)];
    __half hi = __float2half_rn(v);
    __half lo = __float2half_rn(v - __half2float(hi));
    uint32_t off = (uint32_t)(r * 128) + ((uint32_t)(ci * 2) ^ ((uint32_t)(r & 7) << 4));
    *(__half*)&g_wprep[0][kd][off] = hi;
    *(__half*)&g_wprep[1][kd][off] = lo;
}

// ---------------------------------------------------------------------------
__global__ void bias_fill_kernel(const float* __restrict__ bias,
                                 float* __restrict__ out) {
    int idx4 = blockIdx.x * blockDim.x + threadIdx.x;
    if (idx4 >= OUT_F4) return;
    int ch = idx4 / CH_F4;
    float b = __ldg(&bias[ch & 31]);
    reinterpret_cast<float4*>(out)[idx4] = make_float4(b, b, b, b);
}

// ---------------------------------------------------------------------------
// CTA: (ht, d, n). M = 128 rows = 4 h x 32 w. 8 warps, warp wid owns
// m = wid*16 .. wid*16+15 (fragment rows g, g+8). N = 32 co (4 n-tiles of 8).
// A halo plane (per kd): rows = hp*34 + wp, hp in [0,6), wp in [0,34);
// wp = w + kw, hp = hloc + kh. Row = 64 ci fp16, swizzle ^((row&7)<<4).
// ---------------------------------------------------------------------------
__global__ void __launch_bounds__(256, 1)
conv_mma_kernel(const float* __restrict__ x,
                const float* __restrict__ bias,
                float* __restrict__ out) {
    extern __shared__ __align__(16) char smem[];
    const int tid  = threadIdx.x;
    const int lane = tid & 31;
    const int wid  = tid >> 5;
    const int g    = lane >> 2;
    const int t    = lane & 3;

    const int ht = blockIdx.x;        // 0..7
    const int d  = blockIdx.y;        // 0..31
    const int n  = blockIdx.z;        // 0..1
    const int h0 = ht * 4;

    const int m0  = wid * 16 + g;
    const int hl0 = m0 >> 5, wl0 = m0 & 31;
    const int m1  = m0 + 8;
    const int hl1 = m1 >> 5, wl1 = m1 & 31;

    float acc[4][4];
#pragma unroll
    for (int a = 0; a < 4; ++a)
#pragma unroll
        for (int b = 0; b < 4; ++b) acc[a][b] = 0.0f;

    const float* xn = x + (size_t)n * (64 * 32768);

#pragma unroll 1
    for (int kd = 0; kd < 3; ++kd) {
        __syncthreads();   // previous compute done before overwriting A/B
        // ---- zero A hi+lo planes (contiguous 52224 B = 3264 uint4) ----
        {
            uint4 z = make_uint4(0, 0, 0, 0);
            uint4* pz = (uint4*)(smem + SM_AHI);
            for (int i = tid; i < 3264; i += 256) pz[i] = z;
        }
        __syncthreads();
        // ---- copy B tiles for this kd (hi + lo), 2304 uint4 each ----
        {
            const uint4* s0 = (const uint4*)&g_wprep[0][kd][0];
            const uint4* s1 = (const uint4*)&g_wprep[1][kd][0];
            uint4* t0 = (uint4*)(smem + SM_BHI);
            uint4* t1 = (uint4*)(smem + SM_BLO);
            for (int i = tid; i < 2304; i += 256) {
                t0[i] = s0[i];
                t1[i] = s1[i];
            }
        }
        // ---- load x plane gd = d-1+kd: warp = (ci,hp), lane = gw ----
        {
            int gd = d - 1 + kd;
            if (gd >= 0 && gd < 32) {
                const float* xp = xn + gd * 1024;
#pragma unroll 1
                for (int it = 0; it < 48; ++it) {
                    int iter = wid * 48 + it;        // 0..383 = 64 ci x 6 hp
                    int ci = iter / 6;
                    int hp = iter - 6 * ci;
                    int gh = h0 - 1 + hp;
                    if (gh >= 0 && gh < 32) {
                        float v = xp[(size_t)ci * 32768 + gh * 32 + lane];
                        __half hi = __float2half_rn(v);
                        __half lo = __float2half_rn(v - __half2float(hi));
                        int row = hp * 34 + lane + 1;          // wp = gw+1
                        uint32_t off = (uint32_t)(row * 128)
                            + ((uint32_t)(ci * 2) ^ ((uint32_t)(row & 7) << 4));
                        *(__half*)(smem + SM_AHI + off) = hi;
                        *(__half*)(smem + SM_ALO + off) = lo;
                    }
                }
            }
        }
        __syncthreads();

        // ---- compute: 3 passes x 9 taps x 4 ksteps x 4 ntiles ----
#pragma unroll 1
        for (int pass = 0; pass < 3; ++pass) {
            const char* Ab = smem + (pass == 1 ? SM_ALO : SM_AHI);
            const char* Bb = smem + (pass == 2 ? SM_BLO : SM_BHI);
#pragma unroll 1
            for (int t9 = 0; t9 < 9; ++t9) {
                int kh = t9 / 3, kw = t9 - 3 * (t9 / 3);
                int rA0 = (hl0 + kh) * 34 + wl0 + kw;
                int rA1 = (hl1 + kh) * 34 + wl1 + kw;
                const char* pa0 = Ab + rA0 * 128;
                const char* pa1 = Ab + rA1 * 128;
                const uint32_t s0 = (uint32_t)(rA0 & 7) << 4;
                const uint32_t s1 = (uint32_t)(rA1 & 7) << 4;
                const uint32_t sb = (uint32_t)g << 4;
                const char* pb = Bb + (t9 * 32 + g) * 128;
#pragma unroll
                for (int ks = 0; ks < 4; ++ks) {
                    uint32_t cl = (uint32_t)(ks * 32 + t * 4);
                    uint32_t a0 = *(const uint32_t*)(pa0 + (cl ^ s0));
                    uint32_t a1 = *(const uint32_t*)(pa1 + (cl ^ s1));
                    uint32_t a2 = *(const uint32_t*)(pa0 + ((cl + 16) ^ s0));
                    uint32_t a3 = *(const uint32_t*)(pa1 + ((cl + 16) ^ s1));
#pragma unroll
                    for (int nt = 0; nt < 4; ++nt) {
                        const char* pbn = pb + nt * (8 * 128);
                        uint32_t b0 = *(const uint32_t*)(pbn + (cl ^ sb));
                        uint32_t b1 = *(const uint32_t*)(pbn + ((cl + 16) ^ sb));
                        asm volatile(
                            "mma.sync.aligned.m16n8k16.row.col.f32.f16.f16.f32 "
                            "{%0,%1,%2,%3}, {%4,%5,%6,%7}, {%8,%9}, "
                            "{%0,%1,%2,%3};"
                            : "+f"(acc[nt][0]), "+f"(acc[nt][1]),
                              "+f"(acc[nt][2]), "+f"(acc[nt][3])
                            : "r"(a0), "r"(a1), "r"(a2), "r"(a3),
                              "r"(b0), "r"(b1));
                    }
                }
            }
        }
    }

    // ---- epilogue: D[g][2t],D[g][2t+1],D[g+8][2t],D[g+8][2t+1] per n-tile ----
    const int od  = 2 * d + 1;
    const int oh0 = 2 * (h0 + hl0) + 1, ow0 = 2 * wl0 + 1;
    const int oh1 = 2 * (h0 + hl1) + 1, ow1 = 2 * wl1 + 1;
#pragma unroll
    for (int nt = 0; nt < 4; ++nt) {
        int co = nt * 8 + 2 * t;
        float bv0 = __ldg(&bias[co]);
        float bv1 = __ldg(&bias[co + 1]);
        size_t base0 = ((size_t)(n * 32 + co) * OUT_S + od) * (OUT_S * OUT_S);
        float* p00 = out + base0 + oh0 * OUT_S + ow0;
        float* p10 = out + base0 + oh1 * OUT_S + ow1;
        p00[0]         = acc[nt][0] + bv0;
        p00[CH_STRIDE] = acc[nt][1] + bv1;
        p10[0]         = acc[nt][2] + bv0;
        p10[CH_STRIDE] = acc[nt][3] + bv1;
    }
}

// ---------------------------------------------------------------------------
extern "C" void kernel_launch(void* const* d_in, const int* in_sizes, int n_in,
                              void* d_out, int out_size) {
    const float* x = nullptr;
    const float* w = nullptr;
    const float* b = nullptr;
    for (int i = 0; i < n_in; ++i) {
        if (in_sizes[i] == 4194304)    x = (const float*)d_in[i];
        else if (in_sizes[i] == 55296) w = (const float*)d_in[i];
        else if (in_sizes[i] == 32)    b = (const float*)d_in[i];
    }
    float* out = (float*)d_out;

    cudaFuncSetAttribute(conv_mma_kernel,
                         cudaFuncAttributeMaxDynamicSharedMemorySize, SM_TOTAL);

    wprep_kernel<<<(55296 + 255) / 256, 256>>>(w);
    bias_fill_kernel<<<(OUT_F4 + 255) / 256, 256>>>(b, out);

    dim3 grid(8, 32, 2);  // (h-tile, d, n) -> 512 CTAs
    conv_mma_kernel<<<grid, 256, SM_TOTAL>>>(x, b, out);
}

// round 8
// speedup vs baseline: 1.4831x; 1.4831x over previous
#include <cuda_runtime.h>
#include <cstdint>

// x:      (2, 64, 32, 32, 32) fp32
// weight: (64, 32, 3, 3, 3)   fp32
// bias:   (32,)               fp32
// out:    (2, 32, 66, 66, 66) fp32
//
// Core: out[n,co,2z+1] = bias[co] + sum_{ci,tap} W[ci,co,26-tap]*x[n,ci,z-1+k]
// All other outputs bias-only.

#define OUT_S 66
#define CH_STRIDE 287496
#define OUT_TOTAL 18399744
#define OUT_F4 (OUT_TOTAL / 4)
#define CH_F4 (CH_STRIDE / 4)
#define CIC 8
#define NCHUNK 8

// per-buffer smem: xs 8*10*10*10 floats = 32000 B, ws 8*27*32 = 27648 B
#define XS_BYTES 32000
#define BUF_BYTES 59648
#define SM_TOTAL (2 * BUF_BYTES)   // 119296

// Flipped weights staging: [ci][k][co], value = W[ci,co,26-k]. 221184 B.
__device__ __align__(16) float g_wflip[64 * 27 * 32];

// ---------------------------------------------------------------------------
__global__ void wprep_kernel(const float* __restrict__ w) {
    int i = blockIdx.x * blockDim.x + threadIdx.x;   // 64*27*32 = 55296
    if (i >= 55296) return;
    int ci = i / 864;
    int r  = i - ci * 864;
    int k  = r >> 5;
    int co = r & 31;
    g_wflip[i] = w[(ci * 32 + co) * 27 + (26 - k)];
}

// ---------------------------------------------------------------------------
__global__ void bias_fill_kernel(const float* __restrict__ bias,
                                 float* __restrict__ out) {
    int idx4 = blockIdx.x * blockDim.x + threadIdx.x;
    if (idx4 >= OUT_F4) return;
    int ch = idx4 / CH_F4;
    float b = __ldg(&bias[ch & 31]);
    reinterpret_cast<float4*>(out)[idx4] = make_float4(b, b, b, b);
}

// ---------------------------------------------------------------------------
__device__ __forceinline__ void cp4_zfill(uint32_t saddr, const float* g, int ok) {
    asm volatile("cp.async.ca.shared.global [%0], [%1], 4, %2;"
                 :: "r"(saddr), "l"(g), "r"(ok ? 4 : 0) : "memory");
}
__device__ __forceinline__ void cp16(uint32_t saddr, const float4* g) {
    asm volatile("cp.async.cg.shared.global [%0], [%1], 16;"
                 :: "r"(saddr), "l"(g) : "memory");
}
__device__ __forceinline__ void cp_commit() {
    asm volatile("cp.async.commit_group;" ::: "memory");
}
template <int N>
__device__ __forceinline__ void cp_wait() {
    asm volatile("cp.async.wait_group %0;" :: "n"(N) : "memory");
}

// ---------------------------------------------------------------------------
// Block = 512 threads, (8,8,8) z-tile. Thread (coh, ldd, lh, lw):
//   lw = tid&7, lh = (tid>>3)&7, ldd = (tid>>6)&1, coh = tid>>7 (co base 8*coh)
// owns 4 points zloc = ldd + 2p (p<4) at (zh0+lh, zw0+lw), 8 co each.
// Per (ci,tap): 4 LDS.32 (x) + 2 LDS.128 (w broadcast) + 4 mov + 16 fma.f32x2.
// Grid = (4,4,8) = 128 CTAs -> one per SM, single wave.
// Chunk loads (x halo + weights) are cp.async double-buffered.
// ---------------------------------------------------------------------------
__global__ void __launch_bounds__(512, 1)
conv_core_kernel(const float* __restrict__ x,
                 const float* __restrict__ bias,
                 float* __restrict__ out) {
    extern __shared__ __align__(16) char smem[];
    uint32_t sb;
    asm("{ .reg .u64 t; cvta.to.shared.u64 t, %1; cvt.u32.u64 %0, t; }"
        : "=r"(sb) : "l"(smem));

    const int tid = threadIdx.x;
    const int lw  = tid & 7;
    const int lh  = (tid >> 3) & 7;
    const int ldd = (tid >> 6) & 1;
    const int coh = tid >> 7;                 // 0..3 -> co base 8*coh

    const int tw = blockIdx.x, th = blockIdx.y;
    const int nz = blockIdx.z;
    const int n  = nz >> 2;
    const int td = nz & 3;
    const int zd0 = td * 8, zh0 = th * 8, zw0 = tw * 8;

    const float* xn = x + (size_t)n * (64 * 32768);

    // ---- cp.async issue helpers (recomputed indices; ALU is idle) ----
    auto issue_chunk = [&](int cc, int buf) {
        uint32_t sx = sb + buf * BUF_BYTES;
        // x halo: 8000 floats, layout [ci][dd][hh][ww] (10x10x10)
#pragma unroll
        for (int j = 0; j < 16; ++j) {
            int i = tid + j * 512;
            if (i < 8000) {
                int ci = i / 1000;
                int r  = i - ci * 1000;
                int dd = r / 100;
                int r2 = r - dd * 100;
                int hh = r2 / 10;
                int ww = r2 - hh * 10;
                int gd = zd0 - 1 + dd;
                int gh = zh0 - 1 + hh;
                int gw = zw0 - 1 + ww;
                int ok = (gd >= 0 && gd < 32 && gh >= 0 && gh < 32 &&
                          gw >= 0 && gw < 32);
                const float* g = xn + (((size_t)(cc * CIC + ci) * 32 + (gd & 31))
                                       * 32 + (gh & 31)) * 32 + (gw & 31);
                cp4_zfill(sx + i * 4, g, ok);
            }
        }
        // weights: 6912 floats = 1728 float4, contiguous from g_wflip
        uint32_t sw = sx + XS_BYTES;
        const float4* gw4 = (const float4*)(g_wflip + cc * 6912);
#pragma unroll
        for (int j = 0; j < 4; ++j) {
            int i = tid + j * 512;
            if (i < 1728) cp16(sw + i * 16, gw4 + i);
        }
        cp_commit();
    };

    // ---- accumulators: acc[p][j] = point p, co pair {8coh+2j, 8coh+2j+1} ----
    unsigned long long acc[4][4];
#pragma unroll
    for (int p = 0; p < 4; ++p)
#pragma unroll
        for (int j = 0; j < 4; ++j) acc[p][j] = 0ull;

    issue_chunk(0, 0);

#pragma unroll 1
    for (int cc = 0; cc < NCHUNK; ++cc) {
        const int buf = cc & 1;
        if (cc + 1 < NCHUNK) {
            issue_chunk(cc + 1, buf ^ 1);
            cp_wait<1>();
        } else {
            cp_wait<0>();
        }
        __syncthreads();

        const float* xsb = (const float*)(smem + buf * BUF_BYTES);
        const float* wsb = (const float*)(smem + buf * BUF_BYTES + XS_BYTES);

#pragma unroll 1
        for (int ci = 0; ci < CIC; ++ci) {
            // base for point p=0: dd = ldd, hh = lh, ww = lw
            const float* xb = xsb + ci * 1000 + ldd * 100 + lh * 10 + lw;
            const float* wb = wsb + (ci * 27) * 32 + coh * 8;
#pragma unroll
            for (int kd = 0; kd < 3; ++kd)
#pragma unroll
            for (int kh = 0; kh < 3; ++kh)
#pragma unroll
            for (int kw = 0; kw < 3; ++kw) {
                const int off = kd * 100 + kh * 10 + kw;
                unsigned long long xv2[4];
#pragma unroll
                for (int p = 0; p < 4; ++p) {
                    float xv = xb[off + p * 200];
                    asm("mov.b64 %0, {%1, %1};" : "=l"(xv2[p]) : "f"(xv));
                }
                const ulonglong2* wr = (const ulonglong2*)
                    (wb + (kd * 9 + kh * 3 + kw) * 32);
                ulonglong2 w0 = wr[0];   // LDS.128 broadcast: co 8coh..+3
                ulonglong2 w1 = wr[1];   // co 8coh+4..+7
#pragma unroll
                for (int p = 0; p < 4; ++p) {
                    asm("fma.rn.f32x2 %0, %1, %2, %0;"
                        : "+l"(acc[p][0]) : "l"(xv2[p]), "l"(w0.x));
                    asm("fma.rn.f32x2 %0, %1, %2, %0;"
                        : "+l"(acc[p][1]) : "l"(xv2[p]), "l"(w0.y));
                    asm("fma.rn.f32x2 %0, %1, %2, %0;"
                        : "+l"(acc[p][2]) : "l"(xv2[p]), "l"(w1.x));
                    asm("fma.rn.f32x2 %0, %1, %2, %0;"
                        : "+l"(acc[p][3]) : "l"(xv2[p]), "l"(w1.y));
                }
            }
        }
        __syncthreads();   // compute done before buf is overwritten (cc+2)
    }

    // ---- scatter to odd output positions + bias ----
    const int oh = 2 * (zh0 + lh) + 1, ow = 2 * (zw0 + lw) + 1;
#pragma unroll
    for (int p = 0; p < 4; ++p) {
        const int od = 2 * (zd0 + ldd + 2 * p) + 1;
        float* outp = out
            + ((size_t)(n * 32 + coh * 8) * OUT_S + od) * (OUT_S * OUT_S)
            + oh * OUT_S + ow;
#pragma unroll
        for (int j = 0; j < 4; ++j) {
            float2 v;
            asm("mov.b64 {%0, %1}, %2;" : "=f"(v.x), "=f"(v.y)
                                        : "l"(acc[p][j]));
            float b0 = __ldg(&bias[coh * 8 + 2 * j]);
            float b1 = __ldg(&bias[coh * 8 + 2 * j + 1]);
            outp[(size_t)(2 * j) * CH_STRIDE]     = v.x + b0;
            outp[(size_t)(2 * j + 1) * CH_STRIDE] = v.y + b1;
        }
    }
}

// ---------------------------------------------------------------------------
extern "C" void kernel_launch(void* const* d_in, const int* in_sizes, int n_in,
                              void* d_out, int out_size) {
    const float* x = nullptr;
    const float* w = nullptr;
    const float* b = nullptr;
    for (int i = 0; i < n_in; ++i) {
        if (in_sizes[i] == 4194304)    x = (const float*)d_in[i];
        else if (in_sizes[i] == 55296) w = (const float*)d_in[i];
        else if (in_sizes[i] == 32)    b = (const float*)d_in[i];
    }
    float* out = (float*)d_out;

    cudaFuncSetAttribute(conv_core_kernel,
                         cudaFuncAttributeMaxDynamicSharedMemorySize, SM_TOTAL);

    wprep_kernel<<<(55296 + 255) / 256, 256>>>(w);
    bias_fill_kernel<<<(OUT_F4 + 255) / 256, 256>>>(b, out);

    dim3 grid(4, 4, 8);   // 128 CTAs = one per SM, single wave
    conv_core_kernel<<<grid, 512, SM_TOTAL>>>(x, b, out);
}